// round 8
// baseline (speedup 1.0000x reference)
#include <cuda_runtime.h>
#include <cuda_bf16.h>
#include <math.h>

// ---------------------------------------------------------------------------
// CFGGraphEncoder: 3-layer GCN-style encoder.
//   layer(x): agg = segment_sum(x[cols], rows); y = tanh((agg + 2x) @ W + b)
// Linearity transform: h = x @ W  =>  y = tanh(segsum(h[cols]) + 2h + b).
// h buffers ping-pong (A->B->A), selected by TEMPLATE PARAMS inside device
// code. __device__ globals must never be passed as kernel args from host:
// the host-side shadow address is a pageable host pointer, and dereferencing
// it on-GPU triggers HMM page migration (the 128MB device-mem delta that
// failed R5-R7).
// ---------------------------------------------------------------------------

#define N_MAX 131072
#define E_MAX 1600000
#define SCAN_BLK 1024
#define MAX_SCAN_BLOCKS 256

__device__ __align__(128) int   g_cursor[N_MAX];
__device__ __align__(128) int   g_off[N_MAX + 1];
__device__ __align__(128) int   g_csr[E_MAX];
__device__ int   g_blocksum[MAX_SCAN_BLOCKS];
__device__ int   g_blockoff[MAX_SCAN_BLOCKS];
__device__ int   g_hist[64];
__device__ __align__(128) float g_ha[N_MAX * 32];   // h1, then h3
__device__ __align__(128) float g_hb[N_MAX * 32];   // h2

// ---------------------------------------------------------------------------
// Block-wide exclusive scan (blockDim.x multiple of 32, <= 1024).
// ---------------------------------------------------------------------------
__device__ __forceinline__ int block_scan_excl(int v, int* p_total) {
    __shared__ int s_warp[32];
    __shared__ int s_tot;
    const unsigned FULL = 0xffffffffu;
    int lane = threadIdx.x & 31;
    int wid  = threadIdx.x >> 5;
    int nw   = blockDim.x >> 5;

    int incl = v;
#pragma unroll
    for (int d = 1; d < 32; d <<= 1) {
        int t = __shfl_up_sync(FULL, incl, d);
        if (lane >= d) incl += t;
    }
    if (lane == 31) s_warp[wid] = incl;
    __syncthreads();
    if (wid == 0) {
        int wv = (lane < nw) ? s_warp[lane] : 0;
        int wincl = wv;
#pragma unroll
        for (int d = 1; d < 32; d <<= 1) {
            int t = __shfl_up_sync(FULL, wincl, d);
            if (lane >= d) wincl += t;
        }
        if (lane == nw - 1) s_tot = wincl;
        s_warp[lane] = wincl - wv;
    }
    __syncthreads();
    *p_total = s_tot;
    return (incl - v) + s_warp[wid];
}

// ---------------------------------------------------------------------------
// CSR build (unchanged from the verified R3 kernel)
// ---------------------------------------------------------------------------
__global__ void k_zero(int N) {
    int i = blockIdx.x * blockDim.x + threadIdx.x;
    if (i < N) g_cursor[i] = 0;
    if (i < 64) g_hist[i] = 0;
}

__global__ void k_deg(const int* __restrict__ ei, int E) {
    int e = blockIdx.x * blockDim.x + threadIdx.x;
    if (e < E) atomicAdd(&g_cursor[ei[e]], 1);
}

__global__ void k_blocktot(int N) {
    int n = blockIdx.x * blockDim.x + threadIdx.x;
    int v = (n < N) ? g_cursor[n] : 0;
    int tot;
    (void)block_scan_excl(v, &tot);
    if (threadIdx.x == 0) g_blocksum[blockIdx.x] = tot;
}

__global__ void k_scanblocks(int nblocks) {
    int t = threadIdx.x;
    int v = (t < nblocks) ? g_blocksum[t] : 0;
    int tot;
    int excl = block_scan_excl(v, &tot);
    if (t < nblocks) g_blockoff[t] = excl;
}

__global__ void k_scanapply(int N) {
    int n = blockIdx.x * blockDim.x + threadIdx.x;
    int v = (n < N) ? g_cursor[n] : 0;
    int tot;
    int excl = block_scan_excl(v, &tot);
    int offv = g_blockoff[blockIdx.x] + excl;
    if (n < N) {
        g_off[n]    = offv;
        g_cursor[n] = offv;
    }
    if (n == N - 1) g_off[N] = offv + v;
}

__global__ void k_scatter(const int* __restrict__ ei, int E) {
    int e = blockIdx.x * blockDim.x + threadIdx.x;
    if (e < E) {
        int r = ei[e];
        int c = ei[E + e];
        int pos = atomicAdd(&g_cursor[r], 1);
        g_csr[pos] = c;
    }
}

__global__ void k_bhist(const int* __restrict__ bi, int N) {
    __shared__ int sh[64];
    if (threadIdx.x < 64) sh[threadIdx.x] = 0;
    __syncthreads();
    int i = blockIdx.x * blockDim.x + threadIdx.x;
    if (i < N) atomicAdd(&sh[bi[i]], 1);
    __syncthreads();
    if (threadIdx.x < 64 && sh[threadIdx.x] != 0)
        atomicAdd(&g_hist[threadIdx.x], sh[threadIdx.x]);
}

__global__ void k_sizes(float* __restrict__ out_tail) {
    int t = threadIdx.x;
    if (t < 64) out_tail[t] = (float)g_hist[t];
}

// ---------------------------------------------------------------------------
// Dense: h1 = x0 @ W1  (FIN=11). One warp per node, lane = output feature.
// Writes g_ha directly (device-side symbol reference).
// ---------------------------------------------------------------------------
#define WPB 8

__global__ __launch_bounds__(WPB * 32)
void k_dense11(const float* __restrict__ x0,
               const float* __restrict__ W,   // [11, 32]
               int N) {
    __shared__ float Ws[11 * 32];
    for (int i = threadIdx.x; i < 11 * 32; i += blockDim.x) Ws[i] = W[i];
    __syncthreads();

    int warp = threadIdx.x >> 5;
    int lane = threadIdx.x & 31;
    int n = blockIdx.x * WPB + warp;
    if (n >= N) return;
    const unsigned FULL = 0xffffffffu;

    float v = 0.0f;
    if (lane < 11) v = __ldg(&x0[(long long)n * 11 + lane]);

    float acc = 0.0f;
#pragma unroll
    for (int f = 0; f < 11; f++) {
        float af = __shfl_sync(FULL, v, f);
        acc = fmaf(af, Ws[f * 32 + lane], acc);
    }
    g_ha[n * 32 + lane] = acc;
}

// ---------------------------------------------------------------------------
// Fused gather layer in h-space. One warp per node, lane = feature.
//   s = 2*h[n] + sum_{c in nbrs(n)} h[c]        (32-wide rows, 128B aligned)
//   y = tanh(s + b)            -> out96[:, col], and (optionally) h_out = y@Wn
// SRC: 1 = g_ha, 2 = g_hb.  DST: 0 = none, 1 = g_ha, 2 = g_hb.
// Buffers selected INSIDE device code (never passed from host).
// Gather is unrolled x4 with rotating accumulators for MLP.
// ---------------------------------------------------------------------------
template <int SRC, int DST>
__global__ __launch_bounds__(WPB * 32)
void k_gather(const float* __restrict__ bvec,   // [32] this layer's bias
              const float* __restrict__ Wn,     // [32,32] next layer W (or null)
              float* __restrict__ out96,
              int N, int col) {
    __shared__ float Ws[32 * 32];
    __shared__ float bs[32];
    if (DST != 0)
        for (int i = threadIdx.x; i < 32 * 32; i += blockDim.x) Ws[i] = Wn[i];
    if (threadIdx.x < 32) bs[threadIdx.x] = bvec[threadIdx.x];
    __syncthreads();

    const float* __restrict__ h_in = (SRC == 1) ? (const float*)g_ha
                                                : (const float*)g_hb;

    int warp = threadIdx.x >> 5;
    int lane = threadIdx.x & 31;
    int n = blockIdx.x * WPB + warp;
    if (n >= N) return;
    const unsigned FULL = 0xffffffffu;

    int start = g_off[n];
    int end   = g_off[n + 1];

    float s0 = 2.0f * __ldg(&h_in[n * 32 + lane]);
    float s1 = 0.0f, s2 = 0.0f, s3 = 0.0f;

    for (int base = start; base < end; base += 32) {
        int m = end - base;                       // neighbors in this chunk
        int idx = (lane < m) ? g_csr[base + lane] : 0;
#pragma unroll
        for (int j = 0; j < 32; j += 4) {
            int c0 = __shfl_sync(FULL, idx, j);
            int c1 = __shfl_sync(FULL, idx, j + 1);
            int c2 = __shfl_sync(FULL, idx, j + 2);
            int c3 = __shfl_sync(FULL, idx, j + 3);
            if (j     < m) s0 += __ldg(&h_in[c0 * 32 + lane]);
            if (j + 1 < m) s1 += __ldg(&h_in[c1 * 32 + lane]);
            if (j + 2 < m) s2 += __ldg(&h_in[c2 * 32 + lane]);
            if (j + 3 < m) s3 += __ldg(&h_in[c3 * 32 + lane]);
        }
    }

    float y = tanhf((s0 + s1) + (s2 + s3) + bs[lane]);
    out96[(long long)n * 96 + col + lane] = y;

    if (DST != 0) {
        float acc = 0.0f;
#pragma unroll
        for (int f = 0; f < 32; f++) {
            float af = __shfl_sync(FULL, y, f);
            acc = fmaf(af, Ws[f * 32 + lane], acc);
        }
        if (DST == 1) g_ha[n * 32 + lane] = acc;
        else          g_hb[n * 32 + lane] = acc;
    }
}

// ---------------------------------------------------------------------------
// Launch
// ---------------------------------------------------------------------------
extern "C" void kernel_launch(void* const* d_in, const int* in_sizes, int n_in,
                              void* d_out, int out_size) {
    const float* x0 = (const float*)d_in[0];      // [N, 11]
    const int*   ei = (const int*)d_in[1];        // [2, E] int32
    const int*   bi = (const int*)d_in[2];        // [N]    int32
    const float* W1 = (const float*)d_in[3];
    const float* b1 = (const float*)d_in[4];
    const float* W2 = (const float*)d_in[5];
    const float* b2 = (const float*)d_in[6];
    const float* W3 = (const float*)d_in[7];
    const float* b3 = (const float*)d_in[8];
    float* out = (float*)d_out;

    int N = in_sizes[0] / 11;
    int E = in_sizes[1] / 2;
    int tail = out_size - 64;

    int zb = (max(N, 64) + 255) / 256;
    k_zero<<<zb, 256>>>(N);

    int eb = (E + 255) / 256;
    k_deg<<<eb, 256>>>(ei, E);

    int nb = (N + SCAN_BLK - 1) / SCAN_BLK;
    k_blocktot<<<nb, SCAN_BLK>>>(N);
    k_scanblocks<<<1, 128>>>(nb);
    k_scanapply<<<nb, SCAN_BLK>>>(N);

    k_scatter<<<eb, 256>>>(ei, E);

    k_bhist<<<(N + 255) / 256, 256>>>(bi, N);
    k_sizes<<<1, 64>>>(out + tail);

    int lb = (N + WPB - 1) / WPB;
    k_dense11<<<lb, WPB * 32>>>(x0, W1, N);
    // ping-pong: ha(h1) -> hb(h2) -> ha(h3), all selected in device code
    k_gather<1, 2><<<lb, WPB * 32>>>(b1, W2, out, N, 0);
    k_gather<2, 1><<<lb, WPB * 32>>>(b2, W3, out, N, 32);
    k_gather<1, 0><<<lb, WPB * 32>>>(b3, nullptr, out, N, 64);
}

// round 9
// speedup vs baseline: 1.1122x; 1.1122x over previous
#include <cuda_runtime.h>
#include <cuda_bf16.h>
#include <math.h>

// ---------------------------------------------------------------------------
// CFGGraphEncoder: 3-layer GCN-style encoder.
//   layer(x): agg = segment_sum(x[cols], rows); y = tanh((agg + 2x) @ W + b)
// Linearity transform: h = x @ W  =>  y = tanh(segsum(h[cols]) + 2h + b).
// CSR offsets via unordered block-aggregated allocation (no global scan).
// Gather: float4 lanes, 4 neighbor rows per warp-load (LDG.128).
// __device__ globals are only referenced in device code (never passed as
// kernel args from host -- host-side shadow address triggers HMM faults).
// ---------------------------------------------------------------------------

#define N_MAX 131072
#define E_MAX 1600000
#define SCAN_BLK 1024

__device__ __align__(128) int   g_cursor[N_MAX];    // deg, then write cursor
__device__ __align__(128) int   g_off[N_MAX];       // CSR row start
__device__ __align__(128) int   g_len[N_MAX];       // CSR row length
__device__ __align__(128) int   g_csr[E_MAX];       // CSR column indices
__device__ int   g_alloc;                           // global slot allocator
__device__ int   g_hist[64];
__device__ __align__(128) float g_ha[N_MAX * 32];   // h1, then h3
__device__ __align__(128) float g_hb[N_MAX * 32];   // h2

// ---------------------------------------------------------------------------
// Block-wide exclusive scan (blockDim.x multiple of 32, <= 1024).
// ---------------------------------------------------------------------------
__device__ __forceinline__ int block_scan_excl(int v, int* p_total) {
    __shared__ int s_warp[32];
    __shared__ int s_tot;
    const unsigned FULL = 0xffffffffu;
    int lane = threadIdx.x & 31;
    int wid  = threadIdx.x >> 5;
    int nw   = blockDim.x >> 5;

    int incl = v;
#pragma unroll
    for (int d = 1; d < 32; d <<= 1) {
        int t = __shfl_up_sync(FULL, incl, d);
        if (lane >= d) incl += t;
    }
    if (lane == 31) s_warp[wid] = incl;
    __syncthreads();
    if (wid == 0) {
        int wv = (lane < nw) ? s_warp[lane] : 0;
        int wincl = wv;
#pragma unroll
        for (int d = 1; d < 32; d <<= 1) {
            int t = __shfl_up_sync(FULL, wincl, d);
            if (lane >= d) wincl += t;
        }
        if (lane == nw - 1) s_tot = wincl;
        s_warp[lane] = wincl - wv;
    }
    __syncthreads();
    *p_total = s_tot;
    return (incl - v) + s_warp[wid];
}

// ---------------------------------------------------------------------------
// K1: zero counters (cursor, hist, alloc)
// ---------------------------------------------------------------------------
__global__ void k_zero(int N) {
    int i = blockIdx.x * blockDim.x + threadIdx.x;
    if (i < N) g_cursor[i] = 0;
    if (i < 64) g_hist[i] = 0;
    if (i == 0) g_alloc = 0;
}

// ---------------------------------------------------------------------------
// K2: degree count + batch histogram (fused)
// ---------------------------------------------------------------------------
__global__ void k_deg_bhist(const int* __restrict__ ei,
                            const int* __restrict__ bi, int E, int N) {
    __shared__ int sh[64];
    if (threadIdx.x < 64) sh[threadIdx.x] = 0;
    __syncthreads();
    int e = blockIdx.x * blockDim.x + threadIdx.x;
    if (e < E) atomicAdd(&g_cursor[ei[e]], 1);
    if (e < N) atomicAdd(&sh[bi[e]], 1);
    __syncthreads();
    if (threadIdx.x < 64 && sh[threadIdx.x] != 0)
        atomicAdd(&g_hist[threadIdx.x], sh[threadIdx.x]);
}

// ---------------------------------------------------------------------------
// K3: unordered slot allocation (block scan + one atomic per block)
//     + write graph_sizes to the output tail (hist is complete after K2).
// ---------------------------------------------------------------------------
__global__ void k_alloc(int N, float* __restrict__ out_tail) {
    int n = blockIdx.x * blockDim.x + threadIdx.x;
    int v = (n < N) ? g_cursor[n] : 0;
    int tot;
    int excl = block_scan_excl(v, &tot);

    __shared__ int s_base;
    if (threadIdx.x == 0) s_base = atomicAdd(&g_alloc, tot);
    __syncthreads();

    if (n < N) {
        int start = s_base + excl;
        g_off[n]    = start;
        g_len[n]    = v;
        g_cursor[n] = start;   // scatter cursor
    }
    if (blockIdx.x == 0 && threadIdx.x < 64)
        out_tail[threadIdx.x] = (float)g_hist[threadIdx.x];
}

// ---------------------------------------------------------------------------
// K4: scatter edges into CSR slots
// ---------------------------------------------------------------------------
__global__ void k_scatter(const int* __restrict__ ei, int E) {
    int e = blockIdx.x * blockDim.x + threadIdx.x;
    if (e < E) {
        int r = ei[e];
        int c = ei[E + e];
        int pos = atomicAdd(&g_cursor[r], 1);
        g_csr[pos] = c;
    }
}

// ---------------------------------------------------------------------------
// K5: dense h1 = x0 @ W1 (FIN=11). One warp per node, lane = out feature.
// ---------------------------------------------------------------------------
#define WPB 8

__global__ __launch_bounds__(WPB * 32)
void k_dense11(const float* __restrict__ x0,
               const float* __restrict__ W,   // [11, 32]
               int N) {
    __shared__ float Ws[11 * 32];
    for (int i = threadIdx.x; i < 11 * 32; i += blockDim.x) Ws[i] = W[i];
    __syncthreads();

    int warp = threadIdx.x >> 5;
    int lane = threadIdx.x & 31;
    int n = blockIdx.x * WPB + warp;
    if (n >= N) return;
    const unsigned FULL = 0xffffffffu;

    float v = 0.0f;
    if (lane < 11) v = __ldg(&x0[(long long)n * 11 + lane]);

    float acc = 0.0f;
#pragma unroll
    for (int f = 0; f < 11; f++) {
        float af = __shfl_sync(FULL, v, f);
        acc = fmaf(af, Ws[f * 32 + lane], acc);
    }
    g_ha[n * 32 + lane] = acc;
}

// ---------------------------------------------------------------------------
// K6-8: fused gather layer. One warp per node.
// float4 lanes: grp = lane>>3 (which of 4 rows), sub = lane&7 (which 16B).
// Each inner step: ONE LDG.128 per lane covers 4 neighbor rows for the warp.
// Cross-group reduce via shfl_xor(8|16), then transpose to lane=feature.
// SRC: 1=g_ha 2=g_hb; DST: 0=none 1=g_ha 2=g_hb (device-side selection).
// ---------------------------------------------------------------------------
template <int SRC, int DST>
__global__ __launch_bounds__(WPB * 32)
void k_gather(const float* __restrict__ bvec,   // [32] layer bias
              const float* __restrict__ Wn,     // [32,32] next W (or null)
              float* __restrict__ out96,
              int N, int col) {
    __shared__ float Ws[32 * 32];
    __shared__ float bs[32];
    if (DST != 0)
        for (int i = threadIdx.x; i < 32 * 32; i += blockDim.x) Ws[i] = Wn[i];
    if (threadIdx.x < 32) bs[threadIdx.x] = bvec[threadIdx.x];
    __syncthreads();

    const float* __restrict__ h_in = (SRC == 1) ? (const float*)g_ha
                                                : (const float*)g_hb;

    int warp = threadIdx.x >> 5;
    int lane = threadIdx.x & 31;
    int n = blockIdx.x * WPB + warp;
    if (n >= N) return;                 // n is warp-uniform: whole warp exits
    const unsigned FULL = 0xffffffffu;

    int grp = lane >> 3;                // 0..3: row slot within 4-row group
    int sub = lane & 7;                 // 0..7: 16B chunk within row

    // self term (lane = feature layout), overlaps with gather
    float self2 = 2.0f * __ldg(&h_in[n * 32 + lane]);

    int start = g_off[n];
    int len   = g_len[n];
    int end   = start + len;

    float4 acc = make_float4(0.f, 0.f, 0.f, 0.f);

    for (int base = start; base < end; base += 32) {
        int rem = end - base;
        int idx = (lane < rem) ? g_csr[base + lane] : 0;
#pragma unroll
        for (int j = 0; j < 8; j++) {
            int slot = j * 4 + grp;
            int c = __shfl_sync(FULL, idx, slot);
            if (slot < rem) {
                const float4* p = (const float4*)&h_in[c * 32];
                float4 v = __ldg(&p[sub]);
                acc.x += v.x; acc.y += v.y; acc.z += v.z; acc.w += v.w;
            }
        }
    }

    // reduce across the 4 row-groups (lanes grp*8+sub, same sub)
#pragma unroll
    for (int d = 8; d <= 16; d <<= 1) {
        acc.x += __shfl_xor_sync(FULL, acc.x, d);
        acc.y += __shfl_xor_sync(FULL, acc.y, d);
        acc.z += __shfl_xor_sync(FULL, acc.z, d);
        acc.w += __shfl_xor_sync(FULL, acc.w, d);
    }

    // transpose to lane = feature: feature lane -> (sub_src = lane>>2, k = lane&3)
    int src = lane >> 2;                // lane holding my feature (grp=0 copy)
    float tx = __shfl_sync(FULL, acc.x, src);
    float ty = __shfl_sync(FULL, acc.y, src);
    float tz = __shfl_sync(FULL, acc.z, src);
    float tw = __shfl_sync(FULL, acc.w, src);
    int k = lane & 3;
    float s = (k == 0) ? tx : (k == 1) ? ty : (k == 2) ? tz : tw;

    float y = tanhf(s + self2 + bs[lane]);
    out96[(long long)n * 96 + col + lane] = y;

    if (DST != 0) {
        float hacc = 0.0f;
#pragma unroll
        for (int f = 0; f < 32; f++) {
            float af = __shfl_sync(FULL, y, f);
            hacc = fmaf(af, Ws[f * 32 + lane], hacc);
        }
        if (DST == 1) g_ha[n * 32 + lane] = hacc;
        else          g_hb[n * 32 + lane] = hacc;
    }
}

// ---------------------------------------------------------------------------
// Launch
// ---------------------------------------------------------------------------
extern "C" void kernel_launch(void* const* d_in, const int* in_sizes, int n_in,
                              void* d_out, int out_size) {
    const float* x0 = (const float*)d_in[0];      // [N, 11]
    const int*   ei = (const int*)d_in[1];        // [2, E] int32
    const int*   bi = (const int*)d_in[2];        // [N]    int32
    const float* W1 = (const float*)d_in[3];
    const float* b1 = (const float*)d_in[4];
    const float* W2 = (const float*)d_in[5];
    const float* b2 = (const float*)d_in[6];
    const float* W3 = (const float*)d_in[7];
    const float* b3 = (const float*)d_in[8];
    float* out = (float*)d_out;

    int N = in_sizes[0] / 11;
    int E = in_sizes[1] / 2;
    int tail = out_size - 64;

    int zb = (max(N, 64) + 255) / 256;
    k_zero<<<zb, 256>>>(N);

    int eb = (E + 255) / 256;
    k_deg_bhist<<<eb, 256>>>(ei, bi, E, N);

    int nb = (N + SCAN_BLK - 1) / SCAN_BLK;
    k_alloc<<<nb, SCAN_BLK>>>(N, out + tail);

    k_scatter<<<eb, 256>>>(ei, E);

    int lb = (N + WPB - 1) / WPB;
    k_dense11<<<lb, WPB * 32>>>(x0, W1, N);
    // ping-pong: ha(h1) -> hb(h2) -> ha(h3), selected in device code
    k_gather<1, 2><<<lb, WPB * 32>>>(b1, W2, out, N, 0);
    k_gather<2, 1><<<lb, WPB * 32>>>(b2, W3, out, N, 32);
    k_gather<1, 0><<<lb, WPB * 32>>>(b3, nullptr, out, N, 64);
}